// round 5
// baseline (speedup 1.0000x reference)
#include <cuda_runtime.h>

// VideoEmbedding: out[n,d] = sum_k basis(t_n)[k] * W[vid_n, d, k]
// N=400000, D=64, K=13, V=128.
//
// Pipeline (NO global atomics anywhere):
//   k_hist:    weight transpose [v][d][k]->[v][k][d] + per-block smem
//              histogram -> count matrix C[b][v] (plain stores)
//   k_scan:    per-video prefix over blocks + 32-padded segment scan,
//              chunk->video map; folds offsets into the base matrix
//   k_scatter: recompute smem ranks, scatter n-indices to g_sorted
//   k_main:    per 32-chunk: W[v] register-resident (13 f32x2/lane),
//              basis via one __sincosf + double-angle recurrence,
//              smem broadcast, 12 packed fma.rn.f32x2 per n per lane.

static constexpr int D  = 64;
static constexpr int K  = 13;     // 1 + 6 sin + 6 cos
static constexpr int MAXV = 256;
static constexpr int SORT_CAP = 1 << 20;
static constexpr int BSORT = 128;  // blocks in hist/scatter (count-matrix rows)

__device__ float g_wt[MAXV * K * D];        // transposed weights [v][k][d]
__device__ int   g_cnt[BSORT * MAXV];       // counts -> (after scan) bases
__device__ int   g_segend[MAXV];            // segment real end (off + count)
__device__ int   g_sorted[SORT_CAP];        // n indices grouped by video
__device__ int   g_chunkv[SORT_CAP / 32];   // chunk -> video
__device__ int   g_nchunks;

__device__ __forceinline__ unsigned long long ffma2u(unsigned long long a,
                                                     unsigned long long b,
                                                     unsigned long long c) {
    unsigned long long d;
    asm("fma.rn.f32x2 %0, %1, %2, %3;" : "=l"(d) : "l"(a), "l"(b), "l"(c));
    return d;
}
__device__ __forceinline__ unsigned long long splat2(float x) {
    unsigned long long r;
    asm("mov.b64 %0, {%1, %1};" : "=l"(r) : "f"(x));
    return r;
}

// ---------------- hist: transpose + per-block histogram ---------------------
__global__ void __launch_bounds__(512)
k_hist(const float* __restrict__ w, const int* __restrict__ vids,
       int N, int V, int tile) {
    __shared__ int sh[MAXV];
    const int tid = threadIdx.x;
    for (int i = tid; i < MAXV; i += 512) sh[i] = 0;
    __syncthreads();

    // weight transpose (grid-stride over all blocks)
    const int total = V * D * K;
    for (int i = blockIdx.x * 512 + tid; i < total; i += BSORT * 512) {
        int k = i % K;
        int d = (i / K) % D;
        int v = i / (K * D);
        g_wt[(v * K + k) * D + d] = w[i];
    }

    // histogram over this block's tile (tile is 4-aligned)
    const int start = blockIdx.x * tile;
    const int end   = min(start + tile, N);
    const int e4    = end >> 2;
    for (int i4 = (start >> 2) + tid; i4 < e4; i4 += 512) {
        int4 q = reinterpret_cast<const int4*>(vids)[i4];
        atomicAdd(&sh[q.x], 1); atomicAdd(&sh[q.y], 1);
        atomicAdd(&sh[q.z], 1); atomicAdd(&sh[q.w], 1);
    }
    for (int i = (e4 << 2) + tid; i < end; i += 512)
        atomicAdd(&sh[vids[i]], 1);
    __syncthreads();

    for (int i = tid; i < MAXV; i += 512)
        g_cnt[blockIdx.x * MAXV + i] = sh[i];   // plain coalesced store
}

// ---------------- scan: per-video block prefix + padded segment scan --------
__global__ void __launch_bounds__(MAXV)
k_scan() {
    const int v = threadIdx.x;                  // 0..MAXV-1
    // prefix over blocks (loads/stores coalesced across v)
    int run = 0;
#pragma unroll 4
    for (int b = 0; b < BSORT; b++) {
        int c = g_cnt[b * MAXV + v];
        g_cnt[b * MAXV + v] = run;
        run += c;
    }
    // padded exclusive scan over videos
    __shared__ int sc[MAXV];
    const int pad = (run + 31) & ~31;
    sc[v] = pad;
    __syncthreads();
    for (int s = 1; s < MAXV; s <<= 1) {
        int a = (v >= s) ? sc[v - s] : 0;
        __syncthreads();
        sc[v] += a;
        __syncthreads();
    }
    const int off = sc[v] - pad;
    g_segend[v] = off + run;
    // fold segment offset into every block base
#pragma unroll 4
    for (int b = 0; b < BSORT; b++)
        g_cnt[b * MAXV + v] += off;
    // chunk -> video map
    for (int c = off >> 5, ce = (off + pad) >> 5; c < ce; c++)
        g_chunkv[c] = v;
    if (v == MAXV - 1) g_nchunks = sc[v] >> 5;
}

// ---------------- scatter: smem ranks + precomputed bases -------------------
__global__ void __launch_bounds__(512)
k_scatter(const int* __restrict__ vids, int N, int tile) {
    __shared__ int sh[MAXV];     // rank counters
    __shared__ int sb[MAXV];     // this block's bases
    const int tid = threadIdx.x;
    for (int i = tid; i < MAXV; i += 512) {
        sh[i] = 0;
        sb[i] = g_cnt[blockIdx.x * MAXV + i];
    }
    __syncthreads();

    const int start = blockIdx.x * tile;
    const int end   = min(start + tile, N);
    const int e4    = end >> 2;
    for (int i4 = (start >> 2) + tid; i4 < e4; i4 += 512) {
        int4 q = reinterpret_cast<const int4*>(vids)[i4];
        const int base = i4 << 2;
        int r;
        r = atomicAdd(&sh[q.x], 1); g_sorted[sb[q.x] + r] = base;
        r = atomicAdd(&sh[q.y], 1); g_sorted[sb[q.y] + r] = base + 1;
        r = atomicAdd(&sh[q.z], 1); g_sorted[sb[q.z] + r] = base + 2;
        r = atomicAdd(&sh[q.w], 1); g_sorted[sb[q.w] + r] = base + 3;
    }
    for (int i = (e4 << 2) + tid; i < end; i += 512) {
        int v = vids[i];
        int r = atomicAdd(&sh[v], 1);
        g_sorted[sb[v] + r] = i;
    }
}

// ---------------- main: register-resident weights, f32x2 inner loop ---------
__global__ void __launch_bounds__(256)
k_main(const float* __restrict__ times, float* __restrict__ out) {
    __shared__ ulonglong2 smb[8][32 * 9];   // per-warp basis staging
    __shared__ int        sidx[8][32];      // per-warp n indices
    const int lane = threadIdx.x & 31;
    const int wib  = threadIdx.x >> 5;
    const int gw   = (blockIdx.x * blockDim.x + threadIdx.x) >> 5;
    const int nwps = (gridDim.x * blockDim.x) >> 5;
    const int NC   = g_nchunks;

    for (int c = gw; c < NC; c += nwps) {
        const int v   = g_chunkv[c];
        const int idx = g_sorted[c * 32 + lane];  // padded slots stay in [0,N)
        const int seg_end = g_segend[v];

        // W[v] -> registers: lane owns columns d = 2*lane, 2*lane+1
        const float* wp = g_wt + v * (K * D) + 2 * lane;
        unsigned long long w[K];
#pragma unroll
        for (int k = 0; k < K; k++)
            w[k] = *reinterpret_cast<const unsigned long long*>(wp + k * D);

        // basis for this lane's n (garbage on padded lanes — never consumed)
        const float t = times[idx];
        const float a = t * 3.14159265358979323846f;
        float s1, q1; __sincosf(a, &s1, &q1);
        const float s2 = 2.f * s1 * q1, q2 = fmaf(q1, q1, -s1 * s1);
        const float s3 = 2.f * s2 * q2, q3 = fmaf(q2, q2, -s2 * s2);
        const float s4 = 2.f * s3 * q3, q4 = fmaf(q3, q3, -s3 * s3);
        const float s5 = 2.f * s4 * q4, q5 = fmaf(q4, q4, -s4 * s4);
        const float s6 = 2.f * s5 * q5, q6 = fmaf(q5, q5, -s5 * s5);

        ulonglong2* bl = &smb[wib][lane * 9];
        bl[0] = make_ulonglong2(splat2(s1), splat2(s2));
        bl[1] = make_ulonglong2(splat2(s3), splat2(s4));
        bl[2] = make_ulonglong2(splat2(s5), splat2(s6));
        bl[3] = make_ulonglong2(splat2(q1), splat2(q2));
        bl[4] = make_ulonglong2(splat2(q3), splat2(q4));
        bl[5] = make_ulonglong2(splat2(q5), splat2(q6));
        sidx[wib][lane] = idx;
        __syncwarp();

        const int jmax = min(32, seg_end - c * 32);   // warp-uniform, >= 1
        for (int j = 0; j < jmax; j++) {
            const int nn = sidx[wib][j];
            const ulonglong2* bj = &smb[wib][j * 9];
            const ulonglong2 B0 = bj[0], B1 = bj[1], B2 = bj[2];
            const ulonglong2 B3 = bj[3], B4 = bj[4], B5 = bj[5];
            unsigned long long acc = w[0];             // basis[0] == 1
            acc = ffma2u(B0.x, w[1],  acc);
            acc = ffma2u(B0.y, w[2],  acc);
            acc = ffma2u(B1.x, w[3],  acc);
            acc = ffma2u(B1.y, w[4],  acc);
            acc = ffma2u(B2.x, w[5],  acc);
            acc = ffma2u(B2.y, w[6],  acc);
            acc = ffma2u(B3.x, w[7],  acc);
            acc = ffma2u(B3.y, w[8],  acc);
            acc = ffma2u(B4.x, w[9],  acc);
            acc = ffma2u(B4.y, w[10], acc);
            acc = ffma2u(B5.x, w[11], acc);
            acc = ffma2u(B5.y, w[12], acc);
            *reinterpret_cast<unsigned long long*>(out + (long)nn * D + 2 * lane) = acc;
        }
        __syncwarp();
    }
}

extern "C" void kernel_launch(void* const* d_in, const int* in_sizes, int n_in,
                              void* d_out, int out_size) {
    const float* times   = (const float*)d_in[0];
    const int*   vids    = (const int*)d_in[1];
    const float* weights = (const float*)d_in[2];
    float*       out     = (float*)d_out;

    const int N = in_sizes[0];
    int V = in_sizes[2] / (D * K);
    if (V > MAXV) V = MAXV;

    // 4-aligned tile so every block's int4 loads are aligned
    const int tile = (((N + BSORT - 1) / BSORT) + 3) & ~3;

    k_hist<<<BSORT, 512>>>(weights, vids, N, V, tile);
    k_scan<<<1, MAXV>>>();
    k_scatter<<<BSORT, 512>>>(vids, N, tile);

    const int maxchunks = N / 32 + V + 1;
    const int mblocks = (maxchunks + 7) / 8;   // 8 warps per block
    k_main<<<mblocks, 256>>>(times, out);
}

// round 6
// speedup vs baseline: 1.1996x; 1.1996x over previous
#include <cuda_runtime.h>

// VideoEmbedding: out[n,d] = sum_k basis(t_n)[k] * W[vid_n, d, k]
// N=400000, D=64, K=13, V=128.
//
// Two kernels:
//   k_sort: persistent single-wave (128 blocks): weight transpose +
//           per-block smem-rank histogram (ranks held in registers) ->
//           global ticket barrier -> per-block base derivation + padded
//           segment scan + chunk->video map -> scatter. No global atomics
//           on the data path.
//   k_main: per 32-chunk of one video: W[v] register-resident
//           (13 x f32x4 per lane, lane owns 4 columns), basis via one
//           __sincosf + double-angle recurrence, splatted into smem;
//           half-warps process 2 n's per iteration sharing the broadcast
//           LDS and one coalesced STG.128.

static constexpr int D  = 64;
static constexpr int K  = 13;     // 1 + 6 sin + 6 cos
static constexpr int MAXV = 256;
static constexpr int SORT_CAP = 1 << 20;
static constexpr int BSORT = 128;  // persistent blocks (<= SM count)

__device__ float g_wt[MAXV * K * D];        // transposed weights [v][k][d]
__device__ int   g_cnt[BSORT * MAXV];       // per-block count matrix
__device__ int   g_segend[MAXV];            // segment real end (off + count)
__device__ int   g_sorted[SORT_CAP];        // n indices grouped by video
__device__ int   g_chunkv[SORT_CAP / 32];   // chunk -> video
__device__ int   g_nchunks;
__device__ int   g_done;                    // barrier ticket
__device__ int   g_done2;                   // exit ticket (resets both)

typedef unsigned long long ull;

__device__ __forceinline__ ull ffma2u(ull a, ull b, ull c) {
    ull d;
    asm("fma.rn.f32x2 %0, %1, %2, %3;" : "=l"(d) : "l"(a), "l"(b), "l"(c));
    return d;
}
__device__ __forceinline__ ull fmul2u(ull a, ull b) {
    ull d;
    asm("mul.rn.f32x2 %0, %1, %2;" : "=l"(d) : "l"(a), "l"(b));
    return d;
}
__device__ __forceinline__ ull fadd2u(ull a, ull b) {
    ull d;
    asm("add.rn.f32x2 %0, %1, %2;" : "=l"(d) : "l"(a), "l"(b));
    return d;
}
__device__ __forceinline__ ull splat2(float x) {
    ull r;
    asm("mov.b64 %0, {%1, %1};" : "=l"(r) : "f"(x));
    return r;
}

// ---------------- persistent fused sort ------------------------------------
__global__ void __launch_bounds__(512)
k_sort(const float* __restrict__ w, const int* __restrict__ vids,
       int N, int V, int tile) {
    __shared__ int sh[MAXV];      // rank counters / scan scratch
    __shared__ int sbase[MAXV];   // this block's final bases
    const int tid = threadIdx.x, b = blockIdx.x, G = gridDim.x;
    for (int i = tid; i < MAXV; i += 512) sh[i] = 0;
    __syncthreads();

    // weight transpose [v][d][k] -> [v][k][d] (grid-stride)
    const int total = V * D * K;
    for (int i = b * 512 + tid; i < total; i += G * 512) {
        int k = i % K;
        int d = (i / K) % D;
        int v = i / (K * D);
        g_wt[(v * K + k) * D + d] = w[i];
    }

    // histogram with register-held ranks (tile <= 4096 -> <= 2 int4 / thread)
    const int start = b * tile;            // tile is 4-aligned
    const int end   = min(start + tile, N);
    const int s4 = start >> 2, e4 = end >> 2;
    const int i40 = s4 + tid, i41 = i40 + 512;
    int4 q0 = make_int4(0, 0, 0, 0), q1 = make_int4(0, 0, 0, 0);
    int r0a = 0, r0b = 0, r0c = 0, r0d = 0;
    int r1a = 0, r1b = 0, r1c = 0, r1d = 0;
    const bool h0 = (i40 < e4), h1 = (i41 < e4);
    if (h0) {
        q0 = reinterpret_cast<const int4*>(vids)[i40];
        r0a = atomicAdd(&sh[q0.x], 1); r0b = atomicAdd(&sh[q0.y], 1);
        r0c = atomicAdd(&sh[q0.z], 1); r0d = atomicAdd(&sh[q0.w], 1);
    }
    if (h1) {
        q1 = reinterpret_cast<const int4*>(vids)[i41];
        r1a = atomicAdd(&sh[q1.x], 1); r1b = atomicAdd(&sh[q1.y], 1);
        r1c = atomicAdd(&sh[q1.z], 1); r1d = atomicAdd(&sh[q1.w], 1);
    }
    int tval = -1, trk = 0;
    const int ti = (e4 << 2) + tid;
    if (ti < end) { tval = vids[ti]; trk = atomicAdd(&sh[tval], 1); }
    __syncthreads();

    for (int i = tid; i < MAXV; i += 512)
        g_cnt[b * MAXV + i] = sh[i];
    __threadfence();

    // grid barrier (all BSORT blocks co-resident: BSORT <= SM count)
    if (tid == 0) {
        atomicAdd(&g_done, 1);
        volatile int* p = &g_done;
        while (*p < G) { }
    }
    __syncthreads();

    // per-block bases: prior-blocks prefix + padded segment offsets
    int prior = 0, totv = 0;
    if (tid < MAXV) {
        for (int bb = 0; bb < BSORT; bb++) {           // coalesced across tid
            int c = g_cnt[bb * MAXV + tid];
            if (bb < b) prior += c;
            totv += c;
        }
        sh[tid] = (totv + 31) & ~31;                   // padded count
    }
    __syncthreads();
    for (int s = 1; s < MAXV; s <<= 1) {               // inclusive scan
        int a = (tid < MAXV && tid >= s) ? sh[tid - s] : 0;
        __syncthreads();
        if (tid < MAXV) sh[tid] += a;
        __syncthreads();
    }
    if (tid < MAXV) {
        const int pad = (totv + 31) & ~31;
        const int segoff = sh[tid] - pad;              // exclusive padded off
        sbase[tid] = segoff + prior;
        if (b == 0) {
            g_segend[tid] = segoff + totv;
            for (int c = segoff >> 5, ce = (segoff + pad) >> 5; c < ce; c++)
                g_chunkv[c] = tid;
            if (tid == MAXV - 1) g_nchunks = sh[tid] >> 5;
        }
    }
    __syncthreads();

    // scatter
    if (h0) {
        const int base = i40 << 2;
        g_sorted[sbase[q0.x] + r0a] = base;
        g_sorted[sbase[q0.y] + r0b] = base + 1;
        g_sorted[sbase[q0.z] + r0c] = base + 2;
        g_sorted[sbase[q0.w] + r0d] = base + 3;
    }
    if (h1) {
        const int base = i41 << 2;
        g_sorted[sbase[q1.x] + r1a] = base;
        g_sorted[sbase[q1.y] + r1b] = base + 1;
        g_sorted[sbase[q1.z] + r1c] = base + 2;
        g_sorted[sbase[q1.w] + r1d] = base + 3;
    }
    if (tval >= 0) g_sorted[sbase[tval] + trk] = ti;

    __threadfence();
    if (tid == 0) {
        if (atomicAdd(&g_done2, 1) == G - 1) { g_done = 0; g_done2 = 0; }
    }
}

// ---------------- main: 4 cols/lane, 2 n's per iteration --------------------
__global__ void __launch_bounds__(256)
k_main(const float* __restrict__ times, float* __restrict__ out) {
    // per-warp basis staging: 32 slots x 14 ull (12 used, stride 112B ->
    // 16B-aligned, broadcast reads of slot pairs hit disjoint banks)
    __shared__ ull smb[8][32 * 14];
    __shared__ int sidx[8][32];
    const int lane = threadIdx.x & 31;
    const int wib  = threadIdx.x >> 5;
    const int half = lane >> 4;            // 0: even j, 1: odd j
    const int c4   = (lane & 15) * 4;      // 4 owned output columns
    const int gw   = (blockIdx.x * blockDim.x + threadIdx.x) >> 5;
    const int nwps = (gridDim.x * blockDim.x) >> 5;
    const int NC   = g_nchunks;

    for (int c = gw; c < NC; c += nwps) {
        const int v   = g_chunkv[c];
        const int idx = g_sorted[c * 32 + lane];   // padded slots stay 0 (valid)
        const int seg_end = g_segend[v];

        // W[v] -> registers: lane holds 13 x f32x4 for its 4 columns
        const float* wp = g_wt + v * (K * D) + c4;
        ull wA[K], wB[K];
#pragma unroll
        for (int k = 0; k < K; k++) {
            ulonglong2 u = *reinterpret_cast<const ulonglong2*>(wp + k * D);
            wA[k] = u.x; wB[k] = u.y;
        }

        // basis for this lane's n (padding lanes compute garbage, never stored)
        const float t = times[idx];
        const float a = t * 3.14159265358979323846f;
        float s1, q1; __sincosf(a, &s1, &q1);
        const float s2 = 2.f * s1 * q1, q2 = fmaf(q1, q1, -s1 * s1);
        const float s3 = 2.f * s2 * q2, q3 = fmaf(q2, q2, -s2 * s2);
        const float s4 = 2.f * s3 * q3, q4 = fmaf(q3, q3, -s3 * s3);
        const float s5 = 2.f * s4 * q4, q5 = fmaf(q4, q4, -s4 * s4);
        const float s6 = 2.f * s5 * q5, q6 = fmaf(q5, q5, -s5 * s5);

        ulonglong2* bl = reinterpret_cast<ulonglong2*>(&smb[wib][lane * 14]);
        bl[0] = make_ulonglong2(splat2(s1), splat2(s2));
        bl[1] = make_ulonglong2(splat2(s3), splat2(s4));
        bl[2] = make_ulonglong2(splat2(s5), splat2(s6));
        bl[3] = make_ulonglong2(splat2(q1), splat2(q2));
        bl[4] = make_ulonglong2(splat2(q3), splat2(q4));
        bl[5] = make_ulonglong2(splat2(q5), splat2(q6));
        sidx[wib][lane] = idx;
        __syncwarp();

        const int jmax  = min(32, seg_end - c * 32);   // >= 1, warp-uniform
        const int jpmax = (jmax + 1) >> 1;
        for (int jp = 0; jp < jpmax; jp++) {
            const int j0 = 2 * jp + half;              // halves take j pairs
            const int nn = sidx[wib][j0];
            const ulonglong2* bj =
                reinterpret_cast<const ulonglong2*>(&smb[wib][j0 * 14]);
            const ulonglong2 P0 = bj[0], P1 = bj[1], P2 = bj[2];
            const ulonglong2 P3 = bj[3], P4 = bj[4], P5 = bj[5];
            // two chains per accumulator for ILP
            ull a0 = ffma2u(P0.x, wA[1], wA[0]);
            ull a1 = fmul2u(P0.y, wA[2]);
            a0 = ffma2u(P1.x, wA[3], a0);
            a1 = ffma2u(P1.y, wA[4], a1);
            a0 = ffma2u(P2.x, wA[5], a0);
            a1 = ffma2u(P2.y, wA[6], a1);
            a0 = ffma2u(P3.x, wA[7], a0);
            a1 = ffma2u(P3.y, wA[8], a1);
            a0 = ffma2u(P4.x, wA[9], a0);
            a1 = ffma2u(P4.y, wA[10], a1);
            a0 = ffma2u(P5.x, wA[11], a0);
            a1 = ffma2u(P5.y, wA[12], a1);
            ull b0 = ffma2u(P0.x, wB[1], wB[0]);
            ull b1 = fmul2u(P0.y, wB[2]);
            b0 = ffma2u(P1.x, wB[3], b0);
            b1 = ffma2u(P1.y, wB[4], b1);
            b0 = ffma2u(P2.x, wB[5], b0);
            b1 = ffma2u(P2.y, wB[6], b1);
            b0 = ffma2u(P3.x, wB[7], b0);
            b1 = ffma2u(P3.y, wB[8], b1);
            b0 = ffma2u(P4.x, wB[9], b0);
            b1 = ffma2u(P4.y, wB[10], b1);
            b0 = ffma2u(P5.x, wB[11], b0);
            b1 = ffma2u(P5.y, wB[12], b1);
            if (j0 < jmax) {
                *reinterpret_cast<ulonglong2*>(out + (long)nn * D + c4) =
                    make_ulonglong2(fadd2u(a0, a1), fadd2u(b0, b1));
            }
        }
        __syncwarp();
    }
}

extern "C" void kernel_launch(void* const* d_in, const int* in_sizes, int n_in,
                              void* d_out, int out_size) {
    const float* times   = (const float*)d_in[0];
    const int*   vids    = (const int*)d_in[1];
    const float* weights = (const float*)d_in[2];
    float*       out     = (float*)d_out;

    const int N = in_sizes[0];
    int V = in_sizes[2] / (D * K);
    if (V > MAXV) V = MAXV;

    const int tile = (((N + BSORT - 1) / BSORT) + 3) & ~3;  // 4-aligned
    k_sort<<<BSORT, 512>>>(weights, vids, N, V, tile);

    const int maxchunks = N / 32 + V + 1;
    const int mblocks = (maxchunks + 7) / 8;   // 8 warps per block
    k_main<<<mblocks, 256>>>(times, out);
}